// round 11
// baseline (speedup 1.0000x reference)
#include <cuda_runtime.h>
#include <math.h>
#include <stdint.h>

// Shapes: output1 (4,1024,3), output2 (4,4096,3), gt (4,4096,3)
#define BATCH 4
#define NP1 1024
#define NP2 4096
// log2(e)/eps, eps = 0.005
#define K2F 288.5390081777927f
// eps*ln(2)
#define EPSLN2F 0.0034657359027997265f

// scratch (__device__ globals: no allocation allowed).
// EVERY buffer below is fully written before any read within one
// kernel_launch call — no cross-call state, no atomics anywhere.
__device__ float d_gtfps[BATCH * NP1 * 3];
__device__ float d_seeds1[BATCH * 51 * 3];
__device__ float d_seeds2[BATCH * 204 * 3];
__device__ float d_f1[BATCH * NP1];
__device__ float d_g1[BATCH * NP1];
__device__ float d_f2[BATCH * NP2];
__device__ float d_g2[BATCH * NP2];
// partial-sum slots (deterministically summed by finalize)
__device__ float d_emdpart[2 * BATCH * 128];          // slot, b, blk (<=128)
__device__ float d_chpart[4 * BATCH * 16 * 2];        // dir, b, blk (<=16), {s,q}
__device__ float d_upart1[BATCH * 7 * 8];             // b, blk, warp
__device__ float d_upart2[BATCH * 26 * 8];

__device__ __forceinline__ float ex2f(float x) {
    float y; asm("ex2.approx.f32 %0, %1;" : "=f"(y) : "f"(x)); return y;
}
__device__ __forceinline__ float lg2f(float x) {
    float y; asm("lg2.approx.f32 %0, %1;" : "=f"(y) : "f"(x)); return y;
}

// Lowering helpers (validated in R9).
__device__ __forceinline__ float norm_plain(float x, float y, float z) {
    return __fadd_rn(__fadd_rn(__fmul_rn(x, x), __fmul_rn(y, y)), __fmul_rn(z, z));
}
__device__ __forceinline__ float norm_asc(float x, float y, float z) {
    return fmaf(z, z, fmaf(y, y, __fmul_rn(x, x)));
}
__device__ __forceinline__ float dot_asc(float x, float y, float z,
                                         float qx, float qy, float qz) {
    return fmaf(z, qz, fmaf(y, qy, __fmul_rn(x, qx)));
}
__device__ __forceinline__ float sqd_ref(float an, float bn, float dot) {
    float d = fmaf(-2.f, dot, __fadd_rn(an, bn));
    return fmaxf(d, 0.f);
}

// ---------------------------------------------------------------------------
// FPS (reference scan semantics: start 0, dists init 1e10, first-index
// argmax ties). FORM: 0 = ascending FMA, 1 = descending FMA (as R9).
// ---------------------------------------------------------------------------
template <int PP, int FORM>
__global__ void __launch_bounds__(1024) fps_kernel(const float* __restrict__ pcd,
                                                   int npoint,
                                                   float* __restrict__ outc) {
    const int N = PP * 1024;
    int b = blockIdx.x;
    int tid = threadIdx.x;
    const float* Pb = pcd + (size_t)b * N * 3;

    float px[PP], py[PP], pz[PP], dd[PP];
#pragma unroll
    for (int k = 0; k < PP; k++) {
        int idx = tid + k * 1024;
        px[k] = Pb[3 * idx]; py[k] = Pb[3 * idx + 1]; pz[k] = Pb[3 * idx + 2];
        dd[k] = 1e10f;
    }

    __shared__ float rv[32];
    __shared__ int   ri[32];
    __shared__ int   s_far;
    int far = 0;
    int wid = tid >> 5, lane = tid & 31;

    for (int it = 0; it < npoint; ++it) {
        float cx = Pb[3 * far], cy = Pb[3 * far + 1], cz = Pb[3 * far + 2];
        if (tid == 0) {
            float* o = outc + ((size_t)b * npoint + it) * 3;
            o[0] = cx; o[1] = cy; o[2] = cz;
        }
        float bv = -1.f; int bi = N;
#pragma unroll
        for (int k = 0; k < PP; k++) {
            float dx = __fadd_rn(px[k], -cx);
            float dy = __fadd_rn(py[k], -cy);
            float dz = __fadd_rn(pz[k], -cz);
            float d;
            if (FORM == 0)
                d = fmaf(dz, dz, fmaf(dy, dy, __fmul_rn(dx, dx)));
            else
                d = fmaf(dx, dx, fmaf(dy, dy, __fmul_rn(dz, dz)));
            float nd = fminf(dd[k], d);
            dd[k] = nd;
            int idx = tid + k * 1024;
            if (nd > bv || (nd == bv && idx < bi)) { bv = nd; bi = idx; }
        }
#pragma unroll
        for (int off = 16; off; off >>= 1) {
            float ov = __shfl_down_sync(0xffffffffu, bv, off);
            int   oi = __shfl_down_sync(0xffffffffu, bi, off);
            if (ov > bv || (ov == bv && oi < bi)) { bv = ov; bi = oi; }
        }
        if (lane == 0) { rv[wid] = bv; ri[wid] = bi; }
        __syncthreads();
        if (wid == 0) {
            float v2 = rv[lane];
            int   i2 = ri[lane];
#pragma unroll
            for (int off = 16; off; off >>= 1) {
                float ov = __shfl_down_sync(0xffffffffu, v2, off);
                int   oi = __shfl_down_sync(0xffffffffu, i2, off);
                if (ov > v2 || (ov == v2 && oi < i2)) { v2 = ov; i2 = oi; }
            }
            if (lane == 0) s_far = i2;
        }
        __syncthreads();
        far = s_far;
    }
}

// ---------------------------------------------------------------------------
// Sinkhorn half-iteration. hz=1: treat H as literal zero (first half-iter;
// bitwise identical to reading zero-initialized memory). No state reads.
// ---------------------------------------------------------------------------
__global__ void __launch_bounds__(1024) sink_kernel(const float* __restrict__ P,
                                                    const float* __restrict__ H,
                                                    const float* __restrict__ Q,
                                                    float* __restrict__ OUT,
                                                    int N, float logaeps, int hz) {
    extern __shared__ float smem[];
    float4* pts = (float4*)smem;
    float*  hk  = smem + 4 * N;
    __shared__ float redm[1024];
    __shared__ float reds[1024];

    int b = blockIdx.y;
    int tid = threadIdx.x;
    const float* Pb = P + (size_t)b * N * 3;
    const float* Hb = H + (size_t)b * N;

    for (int i = tid; i < N; i += 1024) {
        float x = Pb[3 * i], y = Pb[3 * i + 1], z = Pb[3 * i + 2];
        float pn = fmaf(x, x, fmaf(y, y, z * z));
        pts[i] = make_float4(x, y, z, pn);
        hk[i] = hz ? 0.f : Hb[i] * K2F;
    }
    __syncthreads();

    int col  = (blockIdx.x << 5) + (tid & 31);
    int part = tid >> 5;
    const float* Qp = Q + ((size_t)b * N + col) * 3;
    float qx = Qp[0], qy = Qp[1], qz = Qp[2];
    float qn = fmaf(qx, qx, fmaf(qy, qy, qz * qz));

    int chunk = N >> 5;
    int p0 = part * chunk, p1 = p0 + chunk;
    float m = -1e30f, s = 0.f;
#pragma unroll 4
    for (int p = p0; p < p1; ++p) {
        float4 pt = pts[p];
        float dot = fmaf(pt.x, qx, fmaf(pt.y, qy, pt.z * qz));
        float d   = fmaf(-2.f, dot, pt.w + qn);
        float a   = fmaf(d, -K2F, hk[p]);
        if (a > m) { s = fmaf(s, ex2f(m - a), 1.f); m = a; }
        else        s += ex2f(a - m);
    }
    redm[tid] = m; reds[tid] = s;
    __syncthreads();
    if (tid < 32) {
        float M = redm[tid];
#pragma unroll
        for (int k = 1; k < 32; k++) M = fmaxf(M, redm[k * 32 + tid]);
        float S = 0.f;
#pragma unroll
        for (int k = 0; k < 32; k++) S += reds[k * 32 + tid] * ex2f(redm[k * 32 + tid] - M);
        OUT[(size_t)b * N + col] = logaeps - EPSLN2F * (M + lg2f(S));
    }
}

// ---------------------------------------------------------------------------
// Final EMD distance: per-block partial of sum_i sqrt(dist_i) ->
// d_emdpart[slot*BATCH*128 + b*128 + blockIdx.x]. No atomics.
// ---------------------------------------------------------------------------
__global__ void __launch_bounds__(1024) emddist_kernel(const float* __restrict__ Y,
                                                       const float* __restrict__ G,
                                                       const float* __restrict__ X,
                                                       const float* __restrict__ F,
                                                       int N, int slot) {
    extern __shared__ float smem[];
    float4* pts = (float4*)smem;
    float*  gk  = smem + 4 * N;
    __shared__ float reds[1024];

    int b = blockIdx.y;
    int tid = threadIdx.x;
    const float* Yb = Y + (size_t)b * N * 3;
    const float* Gb = G + (size_t)b * N;

    for (int i = tid; i < N; i += 1024) {
        float x = Yb[3 * i], y = Yb[3 * i + 1], z = Yb[3 * i + 2];
        float pn = fmaf(x, x, fmaf(y, y, z * z));
        pts[i] = make_float4(x, y, z, pn);
        gk[i] = Gb[i] * K2F;
    }
    __syncthreads();

    int col  = (blockIdx.x << 5) + (tid & 31);
    int part = tid >> 5;
    const float* Xp = X + ((size_t)b * N + col) * 3;
    float qx = Xp[0], qy = Xp[1], qz = Xp[2];
    float qn = fmaf(qx, qx, fmaf(qy, qy, qz * qz));
    float fk = F[(size_t)b * N + col] * K2F;

    int chunk = N >> 5;
    int p0 = part * chunk, p1 = p0 + chunk;
    float S = 0.f;
#pragma unroll 4
    for (int p = p0; p < p1; ++p) {
        float4 pt = pts[p];
        float dot = fmaf(pt.x, qx, fmaf(pt.y, qy, pt.z * qz));
        float d   = fmaf(-2.f, dot, pt.w + qn);
        float C   = fmaxf(d, 0.f);
        float arg = fmaf(C, -K2F, fk + gk[p]);
        S = fmaf(ex2f(arg), C, S);
    }
    reds[tid] = S;
    __syncthreads();
    if (tid < 32) {
        float T = 0.f;
#pragma unroll
        for (int k = 0; k < 32; k++) T += reds[k * 32 + tid];
        float v = sqrtf((float)N * T);
#pragma unroll
        for (int off = 16; off; off >>= 1)
            v += __shfl_down_sync(0xffffffffu, v, off);
        if (tid == 0)
            d_emdpart[slot * BATCH * 128 + b * 128 + blockIdx.x] = v;
    }
}

// ---------------------------------------------------------------------------
// Chamfer one direction: per-block partials -> d_chpart[dir][b][blk][{s,q}].
// ---------------------------------------------------------------------------
__global__ void __launch_bounds__(256) nnmin_kernel(const float* __restrict__ Q,
                                                    int Nq,
                                                    const float* __restrict__ P,
                                                    int Np, int dir) {
    extern __shared__ float smem[];
    float4* pts = (float4*)smem;
    __shared__ float w1[8], w2[8];

    int b = blockIdx.y;
    int tid = threadIdx.x;
    const float* Pb = P + (size_t)b * Np * 3;
    for (int i = tid; i < Np; i += 256) {
        float x = Pb[3 * i], y = Pb[3 * i + 1], z = Pb[3 * i + 2];
        pts[i] = make_float4(x, y, z, fmaf(x, x, fmaf(y, y, z * z)));
    }
    __syncthreads();

    int qi = blockIdx.x * 256 + tid;
    float vs = 0.f, vq = 0.f;
    if (qi < Nq) {
        const float* Qp = Q + ((size_t)b * Nq + qi) * 3;
        float qx = Qp[0], qy = Qp[1], qz = Qp[2];
        float qn = fmaf(qx, qx, fmaf(qy, qy, qz * qz));
        float best = 1e30f;
#pragma unroll 4
        for (int j = 0; j < Np; ++j) {
            float4 pt = pts[j];
            float dot = fmaf(pt.x, qx, fmaf(pt.y, qy, pt.z * qz));
            float d   = fmaf(-2.f, dot, pt.w + qn);
            d = fmaxf(d, 0.f);
            best = fminf(best, d);
        }
        vq = best;
        vs = sqrtf(best);
    }
#pragma unroll
    for (int off = 16; off; off >>= 1) {
        vs += __shfl_down_sync(0xffffffffu, vs, off);
        vq += __shfl_down_sync(0xffffffffu, vq, off);
    }
    int lane = tid & 31, wid = tid >> 5;
    if (lane == 0) { w1[wid] = vs; w2[wid] = vq; }
    __syncthreads();
    if (tid == 0) {
        float s1 = 0.f, s2 = 0.f;
#pragma unroll
        for (int k = 0; k < 8; k++) { s1 += w1[k]; s2 += w2[k]; }
        int idx = ((dir * BATCH + b) * 16 + blockIdx.x) * 2;
        d_chpart[idx + 0] = s1;
        d_chpart[idx + 1] = s2;
    }
}

// ---------------------------------------------------------------------------
// PU-GAN uniform loss (R9 numerics, frozen). Membership: matched asc-FMA.
// GDMODE=0: matched asc-FMA gd (o1). GDMODE=1: plain norms + asc dot (o2).
// Per-warp partial -> d_upart1/d_upart2 selected IN DEVICE CODE (the R10 bug
// was passing a __device__ symbol as a host-side kernel argument: the host
// shadow address was written via ATS while finalize read the device symbol).
// ---------------------------------------------------------------------------
template <int GDMODE>
__global__ void __launch_bounds__(256) uniform_kernel(const float* __restrict__ pcd,
                                                      const float* __restrict__ seeds,
                                                      int N, int npoint,
                                                      int nblk) {
    extern __shared__ float smem[];
    float4* cloud = (float4*)smem;         // xyz + asc-FMA norm (membership)
    float*  vpl   = smem + 4 * N;          // plain norms (gd when GDMODE=1)
    __shared__ int lists[8][52];

    float* part = (GDMODE == 0) ? d_upart1 : d_upart2;  // device-side symbol

    int b = blockIdx.y;
    int tid = threadIdx.x;
    int wid = tid >> 5, lane = tid & 31;
    const float* Pb = pcd + (size_t)b * N * 3;
    for (int i = tid; i < N; i += 256) {
        float x = Pb[3 * i], y = Pb[3 * i + 1], z = Pb[3 * i + 2];
        cloud[i] = make_float4(x, y, z, norm_asc(x, y, z));
        vpl[i] = norm_plain(x, y, z);
    }
    __syncthreads();

    int pidx = (b * nblk + blockIdx.x) * 8 + wid;
    int s = blockIdx.x * 8 + wid;
    if (s >= npoint) {
        if (lane == 0) part[pidx] = 0.f;
        return;
    }

    const float* sp = seeds + ((size_t)b * npoint + s) * 3;
    float sx = sp[0], sy = sp[1], sz = sp[2];
    float sn = norm_asc(sx, sy, sz);
    int* list = lists[wid];
    float tot = 0.f;

    const double PCT[5] = {0.004, 0.006, 0.008, 0.01, 0.012};
#pragma unroll 1
    for (int pi = 0; pi < 5; ++pi) {
        double p = PCT[pi];
        int ns = (int)((float)N * (float)p);
        double r = sqrt(p);                    // RADIUS = 1
        float r2 = (float)(r * r);
        double expect_d = sqrt(M_PI * p / (double)ns);
        float expect = (float)expect_d;
        float denom = (float)(expect_d + 1e-8);
        float w = (float)((p * 100.0) * (p * 100.0) /
                          (5.0 * (double)BATCH * (double)npoint));

        // scan cloud in index order, collect first ns in-ball indices
        int cnt = 0;
        for (int base = 0; base < N && cnt < ns; base += 32) {
            int i = base + lane;
            bool in = false;
            if (i < N) {
                float4 pt = cloud[i];
                float dot = dot_asc(sx, sy, sz, pt.x, pt.y, pt.z);
                float d   = sqd_ref(sn, pt.w, dot);
                in = d < r2;
            }
            unsigned bal = __ballot_sync(0xffffffffu, in);
            if (in) {
                int pos = cnt + __popc(bal & ((1u << lane) - 1u));
                if (pos < ns) list[pos] = i;
            }
            cnt += __popc(bal);
            if (cnt > ns) cnt = ns;
        }
        int c = cnt;
        __syncwarp();

        // nearest-neighbor distance inside the (padded) group
        float dsum = 0.f;
        for (int k = lane; k < ns; k += 32) {
            int gi = (k < c) ? list[k] : list[0];
            float4 g = cloud[gi];
            float gn = (GDMODE == 0) ? g.w : vpl[gi];
            float nn = 1e10f;
            for (int j = 0; j < ns; ++j) {
                if (j == k) continue;
                int gj = (j < c) ? list[j] : list[0];
                float4 h = cloud[gj];
                float hn = (GDMODE == 0) ? h.w : vpl[gj];
                float dot = dot_asc(g.x, g.y, g.z, h.x, h.y, h.z);
                float d   = sqd_ref(gn, hn, dot);
                nn = fminf(nn, d);
            }
            dsum += sqrtf(fabsf(__fadd_rn(nn, 1e-8f)));
        }
#pragma unroll
        for (int off = 16; off; off >>= 1)
            dsum += __shfl_down_sync(0xffffffffu, dsum, off);
        if (lane == 0) {
            float mean_d = dsum / (float)ns;
            float df = __fadd_rn(mean_d, -expect);
            tot += (__fmul_rn(df, df) / denom) * w;
        }
        __syncwarp();
    }
    if (lane == 0) part[pidx] = tot;
}

// ---------------------------------------------------------------------------
// finalize: deterministic fixed-order sums of all partials -> scalar outputs.
// layout: o1[12288] o2[49152] emd1[4] emd2[4] cd_p1[4] cd_p2[4] cd_t1[4]
//         cd_t2[4] u1 u2
// ---------------------------------------------------------------------------
__global__ void finalize_kernel(float* __restrict__ out) {
    int tid = threadIdx.x;
    const int base = BATCH * NP1 * 3 + BATCH * NP2 * 3;  // 61440
    if (tid < 4) {
        int b = tid;
        float e1 = 0.f, e2 = 0.f;
        for (int k = 0; k < 32; k++)  e1 += d_emdpart[b * 128 + k];
        for (int k = 0; k < 128; k++) e2 += d_emdpart[BATCH * 128 + b * 128 + k];
        out[base + 0 + b] = e1 / (float)NP1;
        out[base + 4 + b] = e2 / (float)NP2;

        const int cnts[4] = {16, 4, 16, 16};
        float cs[4], cq[4];
        for (int dir = 0; dir < 4; dir++) {
            float s = 0.f, q = 0.f;
            for (int k = 0; k < cnts[dir]; k++) {
                int idx = ((dir * BATCH + b) * 16 + k) * 2;
                s += d_chpart[idx + 0];
                q += d_chpart[idx + 1];
            }
            cs[dir] = s; cq[dir] = q;
        }
        out[base + 8 + b]  = 0.5f * (cs[0] / 4096.f + cs[1] / 1024.f);
        out[base + 12 + b] = 0.5f * (cs[2] / 4096.f + cs[3] / 4096.f);
        out[base + 16 + b] = cq[0] / 4096.f + cq[1] / 1024.f;
        out[base + 20 + b] = cq[2] / 4096.f + cq[3] / 4096.f;
    }
    if (tid == 4) {
        float u = 0.f;
        for (int i = 0; i < BATCH * 7 * 8; i++) u += d_upart1[i];
        out[base + 24] = u;
    }
    if (tid == 5) {
        float u = 0.f;
        for (int i = 0; i < BATCH * 26 * 8; i++) u += d_upart2[i];
        out[base + 25] = u;
    }
}

// ---------------------------------------------------------------------------
extern "C" void kernel_launch(void* const* d_in, const int* in_sizes, int n_in,
                              void* d_out, int out_size) {
    const float* o1 = (const float*)d_in[0];
    const float* o2 = (const float*)d_in[1];
    const float* gt = (const float*)d_in[2];
    float* out = (float*)d_out;

    cudaFuncSetAttribute(sink_kernel, cudaFuncAttributeMaxDynamicSharedMemorySize, 96 * 1024);
    cudaFuncSetAttribute(emddist_kernel, cudaFuncAttributeMaxDynamicSharedMemorySize, 96 * 1024);
    cudaFuncSetAttribute(nnmin_kernel, cudaFuncAttributeMaxDynamicSharedMemorySize, 72 * 1024);
    cudaFuncSetAttribute(uniform_kernel<0>, cudaFuncAttributeMaxDynamicSharedMemorySize, 96 * 1024);
    cudaFuncSetAttribute(uniform_kernel<1>, cudaFuncAttributeMaxDynamicSharedMemorySize, 96 * 1024);

    // pass-through outputs
    cudaMemcpyAsync(out, o1, (size_t)BATCH * NP1 * 3 * sizeof(float),
                    cudaMemcpyDeviceToDevice, 0);
    cudaMemcpyAsync(out + BATCH * NP1 * 3, o2,
                    (size_t)BATCH * NP2 * 3 * sizeof(float),
                    cudaMemcpyDeviceToDevice, 0);

    // FPS (R9 config): gt ascFMA; o1/o2 descFMA.
    fps_kernel<4, 0><<<BATCH, 1024>>>(gt, NP1, d_gtfps);
    fps_kernel<1, 1><<<BATCH, 1024>>>(o1, 51, d_seeds1);
    fps_kernel<4, 1><<<BATCH, 1024>>>(o2, 204, d_seeds2);

    // Sinkhorn emd1: x = o1, y = gt_fps, N = 1024
    {
        int N = NP1;
        float la = -(float)(0.005 * log((double)N));
        size_t sm = (size_t)N * 20;
        dim3 grid(N / 32, BATCH);
        sink_kernel<<<grid, 1024, sm>>>(o1, d_f1, d_gtfps, d_g1, N, la, 1);
        sink_kernel<<<grid, 1024, sm>>>(d_gtfps, d_g1, o1, d_f1, N, la, 0);
        for (int it = 1; it < 10; ++it) {
            sink_kernel<<<grid, 1024, sm>>>(o1, d_f1, d_gtfps, d_g1, N, la, 0);
            sink_kernel<<<grid, 1024, sm>>>(d_gtfps, d_g1, o1, d_f1, N, la, 0);
        }
        emddist_kernel<<<grid, 1024, sm>>>(d_gtfps, d_g1, o1, d_f1, N, 0);
    }
    // Sinkhorn emd2: x = o2, y = gt, N = 4096
    {
        int N = NP2;
        float la = -(float)(0.005 * log((double)N));
        size_t sm = (size_t)N * 20;
        dim3 grid(N / 32, BATCH);
        sink_kernel<<<grid, 1024, sm>>>(o2, d_f2, gt, d_g2, N, la, 1);
        sink_kernel<<<grid, 1024, sm>>>(gt, d_g2, o2, d_f2, N, la, 0);
        for (int it = 1; it < 10; ++it) {
            sink_kernel<<<grid, 1024, sm>>>(o2, d_f2, gt, d_g2, N, la, 0);
            sink_kernel<<<grid, 1024, sm>>>(gt, d_g2, o2, d_f2, N, la, 0);
        }
        emddist_kernel<<<grid, 1024, sm>>>(gt, d_g2, o2, d_f2, N, 1);
    }

    // Chamfer: dirs 0: gt->o1, 1: o1->gt, 2: gt->o2, 3: o2->gt
    nnmin_kernel<<<dim3(16, BATCH), 256, (size_t)NP1 * 16>>>(gt, NP2, o1, NP1, 0);
    nnmin_kernel<<<dim3(4,  BATCH), 256, (size_t)NP2 * 16>>>(o1, NP1, gt, NP2, 1);
    nnmin_kernel<<<dim3(16, BATCH), 256, (size_t)NP2 * 16>>>(gt, NP2, o2, NP2, 2);
    nnmin_kernel<<<dim3(16, BATCH), 256, (size_t)NP2 * 16>>>(o2, NP2, gt, NP2, 3);

    // Uniform losses: o1 matched gd; o2 mismatched gd (R9-validated split).
    uniform_kernel<0><<<dim3(7,  BATCH), 256, (size_t)NP1 * 20>>>(o1, d_seeds1, NP1, 51, 7);
    uniform_kernel<1><<<dim3(26, BATCH), 256, (size_t)NP2 * 20>>>(o2, d_seeds2, NP2, 204, 26);

    finalize_kernel<<<1, 32>>>(out);
}

// round 13
// speedup vs baseline: 1.2938x; 1.2938x over previous
#include <cuda_runtime.h>
#include <math.h>
#include <stdint.h>

// Shapes: output1 (4,1024,3), output2 (4,4096,3), gt (4,4096,3)
#define BATCH 4
#define NP1 1024
#define NP2 4096
// log2(e)/eps, eps = 0.005
#define K2F 288.5390081777927f
// eps*ln(2)
#define EPSLN2F 0.0034657359027997265f

// scratch (__device__ globals). Every buffer fully written before read
// within one call — no cross-call state, no atomics, NO stream/event objects.
__device__ float d_gtfps[BATCH * NP1 * 3];
__device__ float d_seeds1[BATCH * 51 * 3];
__device__ float d_seeds2[BATCH * 204 * 3];
__device__ float d_f1[BATCH * NP1];
__device__ float d_g1[BATCH * NP1];
__device__ float d_f2[BATCH * NP2];
__device__ float d_g2[BATCH * NP2];
__device__ float d_emdpart[2 * BATCH * 128];
__device__ float d_chpart[4 * BATCH * 16 * 2];
__device__ float d_upart1[BATCH * 7 * 8];
__device__ float d_upart2[BATCH * 26 * 8];

__device__ __forceinline__ float ex2f(float x) {
    float y; asm("ex2.approx.f32 %0, %1;" : "=f"(y) : "f"(x)); return y;
}
__device__ __forceinline__ float lg2f(float x) {
    float y; asm("lg2.approx.f32 %0, %1;" : "=f"(y) : "f"(x)); return y;
}

// Lowering helpers (validated R9/R11 — uniform loss is knife-edge, frozen).
__device__ __forceinline__ float norm_plain(float x, float y, float z) {
    return __fadd_rn(__fadd_rn(__fmul_rn(x, x), __fmul_rn(y, y)), __fmul_rn(z, z));
}
__device__ __forceinline__ float norm_asc(float x, float y, float z) {
    return fmaf(z, z, fmaf(y, y, __fmul_rn(x, x)));
}
__device__ __forceinline__ float dot_asc(float x, float y, float z,
                                         float qx, float qy, float qz) {
    return fmaf(z, qz, fmaf(y, qy, __fmul_rn(x, qx)));
}
__device__ __forceinline__ float sqd_ref(float an, float bn, float dot) {
    float d = fmaf(-2.f, dot, __fadd_rn(an, bn));
    return fmaxf(d, 0.f);
}

// ---------------------------------------------------------------------------
// FPS v2: 256 threads, register-resident points, u64-packed argmax.
// Distance rounding per FORM identical to validated kernels; min via fminf;
// argmax = max dist, smallest index on ties (key low word = N-idx)
// -> seeds bit-identical to R11.
// ---------------------------------------------------------------------------
template <int PP, int FORM>
__global__ void __launch_bounds__(256) fps2_kernel(const float* __restrict__ pcd,
                                                   int npoint,
                                                   float* __restrict__ outc) {
    const int NT = 256;
    const int N = PP * NT;
    int b = blockIdx.x;
    int tid = threadIdx.x;
    int lane = tid & 31, wid = tid >> 5;
    const float* Pb = pcd + (size_t)b * N * 3;

    float px[PP], py[PP], pz[PP], dd[PP];
#pragma unroll
    for (int k = 0; k < PP; k++) {
        int idx = tid + k * NT;
        px[k] = Pb[3 * idx]; py[k] = Pb[3 * idx + 1]; pz[k] = Pb[3 * idx + 2];
        dd[k] = 1e10f;
    }

    __shared__ unsigned long long wk[8];
    __shared__ int s_far;
    int far = 0;

    for (int it = 0; it < npoint; ++it) {
        float cx = Pb[3 * far], cy = Pb[3 * far + 1], cz = Pb[3 * far + 2];
        if (tid == 0) {
            float* o = outc + ((size_t)b * npoint + it) * 3;
            o[0] = cx; o[1] = cy; o[2] = cz;
        }
        unsigned long long best = 0ull;
#pragma unroll
        for (int k = 0; k < PP; k++) {
            float dx = __fadd_rn(px[k], -cx);
            float dy = __fadd_rn(py[k], -cy);
            float dz = __fadd_rn(pz[k], -cz);
            float d;
            if (FORM == 0)
                d = fmaf(dz, dz, fmaf(dy, dy, __fmul_rn(dx, dx)));
            else
                d = fmaf(dx, dx, fmaf(dy, dy, __fmul_rn(dz, dz)));
            float nd = fminf(dd[k], d);
            dd[k] = nd;
            int idx = tid + k * NT;
            unsigned long long key =
                ((unsigned long long)__float_as_uint(nd) << 32) |
                (unsigned)(N - idx);
            best = key > best ? key : best;
        }
#pragma unroll
        for (int off = 16; off; off >>= 1) {
            unsigned long long o = __shfl_down_sync(0xffffffffu, best, off);
            best = o > best ? o : best;
        }
        if (lane == 0) wk[wid] = best;
        __syncthreads();
        if (tid == 0) {
            unsigned long long m = wk[0];
#pragma unroll
            for (int w = 1; w < 8; w++) m = wk[w] > m ? wk[w] : m;
            s_far = N - (int)(m & 0xFFFFFFFFull);
        }
        __syncthreads();
        far = s_far;
    }
}

// ---------------------------------------------------------------------------
// Sinkhorn v2: branch-free two-pass LSE with folded constants.
// smem record (x,y,z,hw), hw = hk - K2F*|p|^2:
//   a = fma(x,qx2, fma(y,qy2, fma(z,qz2, hw + c))), qx2 = 2*K2F*qx,
//   c = -K2F*|q|^2. Pass1 max, pass2 sum ex2(a - M).
// ---------------------------------------------------------------------------
__global__ void __launch_bounds__(1024) sink_kernel(const float* __restrict__ P,
                                                    const float* __restrict__ H,
                                                    const float* __restrict__ Q,
                                                    float* __restrict__ OUT,
                                                    int N, float logaeps, int hz) {
    extern __shared__ float smem[];
    float4* pts = (float4*)smem;
    __shared__ float red[1024];
    __shared__ float Mcol[32];

    int b = blockIdx.y;
    int tid = threadIdx.x;
    const float* Pb = P + (size_t)b * N * 3;
    const float* Hb = H + (size_t)b * N;

    for (int i = tid; i < N; i += 1024) {
        float x = Pb[3 * i], y = Pb[3 * i + 1], z = Pb[3 * i + 2];
        float pn = fmaf(x, x, fmaf(y, y, z * z));
        float hk = hz ? 0.f : Hb[i] * K2F;
        pts[i] = make_float4(x, y, z, fmaf(pn, -K2F, hk));
    }
    __syncthreads();

    int col  = (blockIdx.x << 5) + (tid & 31);
    int part = tid >> 5;
    const float* Qp = Q + ((size_t)b * N + col) * 3;
    float qx = Qp[0], qy = Qp[1], qz = Qp[2];
    float qn  = fmaf(qx, qx, fmaf(qy, qy, qz * qz));
    float qx2 = 2.f * K2F * qx;
    float qy2 = 2.f * K2F * qy;
    float qz2 = 2.f * K2F * qz;
    float c   = -K2F * qn;

    int chunk = N >> 5;
    int p0 = part * chunk, p1 = p0 + chunk;

    // pass 1: max
    float m = -1e30f;
#pragma unroll 8
    for (int p = p0; p < p1; ++p) {
        float4 t = pts[p];
        float a = fmaf(t.x, qx2, fmaf(t.y, qy2, fmaf(t.z, qz2, t.w + c)));
        m = fmaxf(m, a);
    }
    red[tid] = m;
    __syncthreads();
    if (tid < 32) {
        float M = red[tid];
#pragma unroll
        for (int k = 1; k < 32; k++) M = fmaxf(M, red[k * 32 + tid]);
        Mcol[tid] = M;
    }
    __syncthreads();

    // pass 2: sum of ex2(a - M)
    float cm = c - Mcol[tid & 31];
    float s = 0.f;
#pragma unroll 8
    for (int p = p0; p < p1; ++p) {
        float4 t = pts[p];
        float a = fmaf(t.x, qx2, fmaf(t.y, qy2, fmaf(t.z, qz2, t.w + cm)));
        s += ex2f(a);
    }
    red[tid] = s;
    __syncthreads();
    if (tid < 32) {
        float S = 0.f;
#pragma unroll
        for (int k = 0; k < 32; k++) S += red[k * 32 + tid];
        OUT[(size_t)b * N + col] = logaeps - EPSLN2F * (Mcol[tid] + lg2f(S));
    }
}

// ---------------------------------------------------------------------------
// Final EMD distance (unchanged).
// ---------------------------------------------------------------------------
__global__ void __launch_bounds__(1024) emddist_kernel(const float* __restrict__ Y,
                                                       const float* __restrict__ G,
                                                       const float* __restrict__ X,
                                                       const float* __restrict__ F,
                                                       int N, int slot) {
    extern __shared__ float smem[];
    float4* pts = (float4*)smem;
    float*  gk  = smem + 4 * N;
    __shared__ float reds[1024];

    int b = blockIdx.y;
    int tid = threadIdx.x;
    const float* Yb = Y + (size_t)b * N * 3;
    const float* Gb = G + (size_t)b * N;

    for (int i = tid; i < N; i += 1024) {
        float x = Yb[3 * i], y = Yb[3 * i + 1], z = Yb[3 * i + 2];
        float pn = fmaf(x, x, fmaf(y, y, z * z));
        pts[i] = make_float4(x, y, z, pn);
        gk[i] = Gb[i] * K2F;
    }
    __syncthreads();

    int col  = (blockIdx.x << 5) + (tid & 31);
    int part = tid >> 5;
    const float* Xp = X + ((size_t)b * N + col) * 3;
    float qx = Xp[0], qy = Xp[1], qz = Xp[2];
    float qn = fmaf(qx, qx, fmaf(qy, qy, qz * qz));
    float fk = F[(size_t)b * N + col] * K2F;

    int chunk = N >> 5;
    int p0 = part * chunk, p1 = p0 + chunk;
    float S = 0.f;
#pragma unroll 4
    for (int p = p0; p < p1; ++p) {
        float4 pt = pts[p];
        float dot = fmaf(pt.x, qx, fmaf(pt.y, qy, pt.z * qz));
        float d   = fmaf(-2.f, dot, pt.w + qn);
        float C   = fmaxf(d, 0.f);
        float arg = fmaf(C, -K2F, fk + gk[p]);
        S = fmaf(ex2f(arg), C, S);
    }
    reds[tid] = S;
    __syncthreads();
    if (tid < 32) {
        float T = 0.f;
#pragma unroll
        for (int k = 0; k < 32; k++) T += reds[k * 32 + tid];
        float v = sqrtf((float)N * T);
#pragma unroll
        for (int off = 16; off; off >>= 1)
            v += __shfl_down_sync(0xffffffffu, v, off);
        if (tid == 0)
            d_emdpart[slot * BATCH * 128 + b * 128 + blockIdx.x] = v;
    }
}

// ---------------------------------------------------------------------------
// Chamfer one direction (unchanged).
// ---------------------------------------------------------------------------
__global__ void __launch_bounds__(256) nnmin_kernel(const float* __restrict__ Q,
                                                    int Nq,
                                                    const float* __restrict__ P,
                                                    int Np, int dir) {
    extern __shared__ float smem[];
    float4* pts = (float4*)smem;
    __shared__ float w1[8], w2[8];

    int b = blockIdx.y;
    int tid = threadIdx.x;
    const float* Pb = P + (size_t)b * Np * 3;
    for (int i = tid; i < Np; i += 256) {
        float x = Pb[3 * i], y = Pb[3 * i + 1], z = Pb[3 * i + 2];
        pts[i] = make_float4(x, y, z, fmaf(x, x, fmaf(y, y, z * z)));
    }
    __syncthreads();

    int qi = blockIdx.x * 256 + tid;
    float vs = 0.f, vq = 0.f;
    if (qi < Nq) {
        const float* Qp = Q + ((size_t)b * Nq + qi) * 3;
        float qx = Qp[0], qy = Qp[1], qz = Qp[2];
        float qn = fmaf(qx, qx, fmaf(qy, qy, qz * qz));
        float best = 1e30f;
#pragma unroll 4
        for (int j = 0; j < Np; ++j) {
            float4 pt = pts[j];
            float dot = fmaf(pt.x, qx, fmaf(pt.y, qy, pt.z * qz));
            float d   = fmaf(-2.f, dot, pt.w + qn);
            d = fmaxf(d, 0.f);
            best = fminf(best, d);
        }
        vq = best;
        vs = sqrtf(best);
    }
#pragma unroll
    for (int off = 16; off; off >>= 1) {
        vs += __shfl_down_sync(0xffffffffu, vs, off);
        vq += __shfl_down_sync(0xffffffffu, vq, off);
    }
    int lane = tid & 31, wid = tid >> 5;
    if (lane == 0) { w1[wid] = vs; w2[wid] = vq; }
    __syncthreads();
    if (tid == 0) {
        float s1 = 0.f, s2 = 0.f;
#pragma unroll
        for (int k = 0; k < 8; k++) { s1 += w1[k]; s2 += w2[k]; }
        int idx = ((dir * BATCH + b) * 16 + blockIdx.x) * 2;
        d_chpart[idx + 0] = s1;
        d_chpart[idx + 1] = s2;
    }
}

// ---------------------------------------------------------------------------
// PU-GAN uniform loss (R11 numerics FROZEN — knife-edge validated).
// ---------------------------------------------------------------------------
template <int GDMODE>
__global__ void __launch_bounds__(256) uniform_kernel(const float* __restrict__ pcd,
                                                      const float* __restrict__ seeds,
                                                      int N, int npoint,
                                                      int nblk) {
    extern __shared__ float smem[];
    float4* cloud = (float4*)smem;
    float*  vpl   = smem + 4 * N;
    __shared__ int lists[8][52];

    float* part = (GDMODE == 0) ? d_upart1 : d_upart2;

    int b = blockIdx.y;
    int tid = threadIdx.x;
    int wid = tid >> 5, lane = tid & 31;
    const float* Pb = pcd + (size_t)b * N * 3;
    for (int i = tid; i < N; i += 256) {
        float x = Pb[3 * i], y = Pb[3 * i + 1], z = Pb[3 * i + 2];
        cloud[i] = make_float4(x, y, z, norm_asc(x, y, z));
        vpl[i] = norm_plain(x, y, z);
    }
    __syncthreads();

    int pidx = (b * nblk + blockIdx.x) * 8 + wid;
    int s = blockIdx.x * 8 + wid;
    if (s >= npoint) {
        if (lane == 0) part[pidx] = 0.f;
        return;
    }

    const float* sp = seeds + ((size_t)b * npoint + s) * 3;
    float sx = sp[0], sy = sp[1], sz = sp[2];
    float sn = norm_asc(sx, sy, sz);
    int* list = lists[wid];
    float tot = 0.f;

    const double PCT[5] = {0.004, 0.006, 0.008, 0.01, 0.012};
#pragma unroll 1
    for (int pi = 0; pi < 5; ++pi) {
        double p = PCT[pi];
        int ns = (int)((float)N * (float)p);
        double r = sqrt(p);
        float r2 = (float)(r * r);
        double expect_d = sqrt(M_PI * p / (double)ns);
        float expect = (float)expect_d;
        float denom = (float)(expect_d + 1e-8);
        float w = (float)((p * 100.0) * (p * 100.0) /
                          (5.0 * (double)BATCH * (double)npoint));

        int cnt = 0;
        for (int base = 0; base < N && cnt < ns; base += 32) {
            int i = base + lane;
            bool in = false;
            if (i < N) {
                float4 pt = cloud[i];
                float dot = dot_asc(sx, sy, sz, pt.x, pt.y, pt.z);
                float d   = sqd_ref(sn, pt.w, dot);
                in = d < r2;
            }
            unsigned bal = __ballot_sync(0xffffffffu, in);
            if (in) {
                int pos = cnt + __popc(bal & ((1u << lane) - 1u));
                if (pos < ns) list[pos] = i;
            }
            cnt += __popc(bal);
            if (cnt > ns) cnt = ns;
        }
        int c = cnt;
        __syncwarp();

        float dsum = 0.f;
        for (int k = lane; k < ns; k += 32) {
            int gi = (k < c) ? list[k] : list[0];
            float4 g = cloud[gi];
            float gn = (GDMODE == 0) ? g.w : vpl[gi];
            float nn = 1e10f;
            for (int j = 0; j < ns; ++j) {
                if (j == k) continue;
                int gj = (j < c) ? list[j] : list[0];
                float4 h = cloud[gj];
                float hn = (GDMODE == 0) ? h.w : vpl[gj];
                float dot = dot_asc(g.x, g.y, g.z, h.x, h.y, h.z);
                float d   = sqd_ref(gn, hn, dot);
                nn = fminf(nn, d);
            }
            dsum += sqrtf(fabsf(__fadd_rn(nn, 1e-8f)));
        }
#pragma unroll
        for (int off = 16; off; off >>= 1)
            dsum += __shfl_down_sync(0xffffffffu, dsum, off);
        if (lane == 0) {
            float mean_d = dsum / (float)ns;
            float df = __fadd_rn(mean_d, -expect);
            tot += (__fmul_rn(df, df) / denom) * w;
        }
        __syncwarp();
    }
    if (lane == 0) part[pidx] = tot;
}

// ---------------------------------------------------------------------------
// finalize (unchanged).
// ---------------------------------------------------------------------------
__global__ void finalize_kernel(float* __restrict__ out) {
    int tid = threadIdx.x;
    const int base = BATCH * NP1 * 3 + BATCH * NP2 * 3;  // 61440
    if (tid < 4) {
        int b = tid;
        float e1 = 0.f, e2 = 0.f;
        for (int k = 0; k < 32; k++)  e1 += d_emdpart[b * 128 + k];
        for (int k = 0; k < 128; k++) e2 += d_emdpart[BATCH * 128 + b * 128 + k];
        out[base + 0 + b] = e1 / (float)NP1;
        out[base + 4 + b] = e2 / (float)NP2;

        const int cnts[4] = {16, 4, 16, 16};
        float cs[4], cq[4];
        for (int dir = 0; dir < 4; dir++) {
            float s = 0.f, q = 0.f;
            for (int k = 0; k < cnts[dir]; k++) {
                int idx = ((dir * BATCH + b) * 16 + k) * 2;
                s += d_chpart[idx + 0];
                q += d_chpart[idx + 1];
            }
            cs[dir] = s; cq[dir] = q;
        }
        out[base + 8 + b]  = 0.5f * (cs[0] / 4096.f + cs[1] / 1024.f);
        out[base + 12 + b] = 0.5f * (cs[2] / 4096.f + cs[3] / 4096.f);
        out[base + 16 + b] = cq[0] / 4096.f + cq[1] / 1024.f;
        out[base + 20 + b] = cq[2] / 4096.f + cq[3] / 4096.f;
    }
    if (tid == 4) {
        float u = 0.f;
        for (int i = 0; i < BATCH * 7 * 8; i++) u += d_upart1[i];
        out[base + 24] = u;
    }
    if (tid == 5) {
        float u = 0.f;
        for (int i = 0; i < BATCH * 26 * 8; i++) u += d_upart2[i];
        out[base + 25] = u;
    }
}

// ---------------------------------------------------------------------------
extern "C" void kernel_launch(void* const* d_in, const int* in_sizes, int n_in,
                              void* d_out, int out_size) {
    const float* o1 = (const float*)d_in[0];
    const float* o2 = (const float*)d_in[1];
    const float* gt = (const float*)d_in[2];
    float* out = (float*)d_out;

    cudaFuncSetAttribute(sink_kernel, cudaFuncAttributeMaxDynamicSharedMemorySize, 96 * 1024);
    cudaFuncSetAttribute(emddist_kernel, cudaFuncAttributeMaxDynamicSharedMemorySize, 96 * 1024);
    cudaFuncSetAttribute(nnmin_kernel, cudaFuncAttributeMaxDynamicSharedMemorySize, 72 * 1024);
    cudaFuncSetAttribute(uniform_kernel<0>, cudaFuncAttributeMaxDynamicSharedMemorySize, 96 * 1024);
    cudaFuncSetAttribute(uniform_kernel<1>, cudaFuncAttributeMaxDynamicSharedMemorySize, 96 * 1024);

    // pass-through outputs
    cudaMemcpyAsync(out, o1, (size_t)BATCH * NP1 * 3 * sizeof(float),
                    cudaMemcpyDeviceToDevice, 0);
    cudaMemcpyAsync(out + BATCH * NP1 * 3, o2,
                    (size_t)BATCH * NP2 * 3 * sizeof(float),
                    cudaMemcpyDeviceToDevice, 0);

    // FPS (R11-bit-identical seeds): gt ascFMA; o1/o2 descFMA.
    fps2_kernel<16, 0><<<BATCH, 256>>>(gt, NP1, d_gtfps);
    fps2_kernel<4,  1><<<BATCH, 256>>>(o1, 51, d_seeds1);
    fps2_kernel<16, 1><<<BATCH, 256>>>(o2, 204, d_seeds2);

    // Sinkhorn emd1: x = o1, y = gt_fps, N = 1024
    {
        int N = NP1;
        float la = -(float)(0.005 * log((double)N));
        size_t smS = (size_t)N * 16;
        size_t smE = (size_t)N * 20;
        dim3 grid(N / 32, BATCH);
        sink_kernel<<<grid, 1024, smS>>>(o1, d_f1, d_gtfps, d_g1, N, la, 1);
        sink_kernel<<<grid, 1024, smS>>>(d_gtfps, d_g1, o1, d_f1, N, la, 0);
        for (int it = 1; it < 10; ++it) {
            sink_kernel<<<grid, 1024, smS>>>(o1, d_f1, d_gtfps, d_g1, N, la, 0);
            sink_kernel<<<grid, 1024, smS>>>(d_gtfps, d_g1, o1, d_f1, N, la, 0);
        }
        emddist_kernel<<<grid, 1024, smE>>>(d_gtfps, d_g1, o1, d_f1, N, 0);
    }
    // Sinkhorn emd2: x = o2, y = gt, N = 4096
    {
        int N = NP2;
        float la = -(float)(0.005 * log((double)N));
        size_t smS = (size_t)N * 16;
        size_t smE = (size_t)N * 20;
        dim3 grid(N / 32, BATCH);
        sink_kernel<<<grid, 1024, smS>>>(o2, d_f2, gt, d_g2, N, la, 1);
        sink_kernel<<<grid, 1024, smS>>>(gt, d_g2, o2, d_f2, N, la, 0);
        for (int it = 1; it < 10; ++it) {
            sink_kernel<<<grid, 1024, smS>>>(o2, d_f2, gt, d_g2, N, la, 0);
            sink_kernel<<<grid, 1024, smS>>>(gt, d_g2, o2, d_f2, N, la, 0);
        }
        emddist_kernel<<<grid, 1024, smE>>>(gt, d_g2, o2, d_f2, N, 1);
    }

    // Chamfer: dirs 0: gt->o1, 1: o1->gt, 2: gt->o2, 3: o2->gt
    nnmin_kernel<<<dim3(16, BATCH), 256, (size_t)NP1 * 16>>>(gt, NP2, o1, NP1, 0);
    nnmin_kernel<<<dim3(4,  BATCH), 256, (size_t)NP2 * 16>>>(o1, NP1, gt, NP2, 1);
    nnmin_kernel<<<dim3(16, BATCH), 256, (size_t)NP2 * 16>>>(gt, NP2, o2, NP2, 2);
    nnmin_kernel<<<dim3(16, BATCH), 256, (size_t)NP2 * 16>>>(o2, NP2, gt, NP2, 3);

    // Uniform losses: o1 matched gd; o2 mismatched gd.
    uniform_kernel<0><<<dim3(7,  BATCH), 256, (size_t)NP1 * 20>>>(o1, d_seeds1, NP1, 51, 7);
    uniform_kernel<1><<<dim3(26, BATCH), 256, (size_t)NP2 * 20>>>(o2, d_seeds2, NP2, 204, 26);

    finalize_kernel<<<1, 32>>>(out);
}